// round 15
// baseline (speedup 1.0000x reference)
#include <cuda_runtime.h>

#define BB 8
#define TT 128
#define DD 256

__device__ __forceinline__ float ex2f(float x) {
    float y; asm("ex2.approx.f32 %0, %1;" : "=f"(y) : "f"(x)); return y;
}

#define MAGIC 12582912.0f   // 1.5 * 2^23
#define C1 0.69314720f
#define C2 0.24022643f
#define C3 0.05550328f
#define C4 0.00967579f

// Fused-product fma-pipe exp2(d*x): 8 issues, no MUFU.
// c=fma(d,x,M); n=c-M; f=fma(d,x,-n); deg-4 Horner; scale by 2^n via one IMAD
// (low 9 bits of MAGIC's float bits shift out of the 32-bit product exactly).
__device__ __forceinline__ float ex2_poly(float d, float x) {
    const float c = fmaf(d, x, MAGIC);
    const float n = c - MAGIC;
    const float f = fmaf(d, x, -n);         // exact reduced argument
    float p = fmaf(f, C4, C3);
    p = fmaf(f, p, C2);
    p = fmaf(f, p, C1);
    p = fmaf(f, p, 1.0f);                   // 2^f
    return __int_as_float(__float_as_int(p) + __float_as_int(c) * 8388608);
}

// One block per (b,t). Thread tid = (rp, cg): cols 8cg..8cg+7, rows 32rp..32rp+31.
// 6 cols via MUFU.EX2, 2 cols via fma-pipe poly: MUFU floor and issue floor
// balanced at ~75% of the pure-MUFU floor. No packed ops, no shfl, no predicates.
__global__ __launch_bounds__(DD) void attn_fused_kernel(
    const float* __restrict__ dec_t,   // [B, D]
    const float* __restrict__ enc_out, // [B, T, D]
    float* __restrict__ out            // [B, D], pre-zeroed
) {
    __shared__ float s_dec[DD];          // dec * log2e
    __shared__ float s_rp[DD][33];       // row partials: [row][colgroup], stride-33
    __shared__ float s_cp[8][DD];        // colsum partials per row-part

    const int bt  = blockIdx.x;          // b*T + t
    const int b   = bt >> 7;
    const int tid = threadIdx.x;
    const int cg  = tid & 31;            // col group (8 cols) = lane
    const int rp  = tid >> 5;            // row part (32 rows) = warp

    const float L2E = 1.4426950408889634f;
    s_dec[tid] = dec_t[b * DD + tid] * L2E;

    const float4 xa = *(const float4*)(enc_out + bt * DD + cg * 8);
    const float4 xb = *(const float4*)(enc_out + bt * DD + cg * 8 + 4);

    __syncthreads();

    float c0 = 0.f, c1 = 0.f, c2 = 0.f, c3 = 0.f;
    float c4 = 0.f, c5 = 0.f, c6 = 0.f, c7 = 0.f;

    const float* dbase = &s_dec[rp * 32];
    float* rbase = &s_rp[rp * 32][cg];

#pragma unroll
    for (int i = 0; i < 32; i++) {
        const float d = dbase[i];               // warp-uniform, immediate offset
        const float e0 = ex2f(d * xa.x);
        const float e1 = ex2f(d * xa.y);
        const float e2 = ex2f(d * xa.z);
        const float e3 = ex2f(d * xa.w);
        const float e4 = ex2f(d * xb.x);
        const float e5 = ex2f(d * xb.y);
        const float e6 = ex2_poly(d, xb.z);     // fma-pipe path
        const float e7 = ex2_poly(d, xb.w);     // fma-pipe path
        c0 += e0; c1 += e1; c2 += e2; c3 += e3;
        c4 += e4; c5 += e5; c6 += e6; c7 += e7;
        rbase[i * 33] = ((e0 + e1) + (e2 + e3)) + ((e4 + e5) + (e6 + e7));
    }

    // spill colsum partials (2x STS.128)
    *(float4*)&s_cp[rp][cg * 8]     = make_float4(c0, c1, c2, c3);
    *(float4*)&s_cp[rp][cg * 8 + 4] = make_float4(c4, c5, c6, c7);
    __syncthreads();

    // rowsum of row tid (same thread outputs column q = tid); stride-33 reads:
    // lanes differ by 33 mod 32 = 1 bank -> conflict-free
    float rs = 0.f;
#pragma unroll
    for (int j = 0; j < 32; j++) rs += s_rp[tid][j];

    float cs = 0.f;
#pragma unroll
    for (int r = 0; r < 8; r++) cs += s_cp[r][tid];

    const float x = enc_out[bt * DD + tid];
    atomicAdd(&out[b * DD + tid], __fdividef(x * cs, rs));
}

extern "C" void kernel_launch(void* const* d_in, const int* in_sizes, int n_in,
                              void* d_out, int out_size) {
    const float* dec_t   = (const float*)d_in[0];
    const float* enc_out = (const float*)d_in[1];
    if (n_in >= 2 && in_sizes[0] == BB * TT * DD && in_sizes[1] == BB * DD) {
        dec_t   = (const float*)d_in[1];
        enc_out = (const float*)d_in[0];
    }
    float* out = (float*)d_out;

    cudaMemsetAsync(out, 0, BB * DD * sizeof(float), 0);
    attn_fused_kernel<<<BB * TT, DD>>>(dec_t, enc_out, out);
}

// round 16
// speedup vs baseline: 1.8611x; 1.8611x over previous
#include <cuda_runtime.h>

#define BB 8
#define TT 128
#define DD 256

typedef unsigned long long u64;

__device__ __forceinline__ float ex2f(float x) {
    float y; asm("ex2.approx.f32 %0, %1;" : "=f"(y) : "f"(x)); return y;
}
// packed add on float2 (register pairs)
__device__ __forceinline__ float2 padd2(float2 a, float2 b) {
    float2 r;
    asm("add.rn.f32x2 %0, %1, %2;"
        : "=l"(*(u64*)&r) : "l"(*(u64*)&a), "l"(*(u64*)&b));
    return r;
}

#define MAGIC 12582912.0f   // 1.5 * 2^23
// deg-3 economized minimax for 2^f on [-0.5, 0.5], rel err ~8e-5
#define P0 0.99992496f
#define P1 0.69312108f
#define P2 0.24262073f
#define P3 0.05592071f

// fma-pipe exp2(d*x): 7 issues, no MUFU.
__device__ __forceinline__ float ex2_poly(float d, float x) {
    const float c = fmaf(d, x, MAGIC);      // n=round(d*x) in mantissa
    const float n = c - MAGIC;
    const float f = fmaf(d, x, -n);         // exact reduced argument
    float p = fmaf(f, P3, P2);
    p = fmaf(f, p, P1);
    p = fmaf(f, p, P0);                     // ~2^f
    // exact 2^n scale: bits(c)*2^23 == n<<23 in 32-bit arithmetic
    return __int_as_float(__float_as_int(p) + __float_as_int(c) * 8388608);
}

// One block per (b,t). Thread tid = (rp, cg): cols 8cg..8cg+7, rows 32rp..32rp+31.
// 7 cols via MUFU.EX2, 1 col via fma-pipe poly: balances MUFU floor (7/8 * 28.3k)
// against issue floor (~24.5k) per SMSP. Otherwise identical to the best R12 kernel.
__global__ __launch_bounds__(DD) void attn_fused_kernel(
    const float* __restrict__ dec_t,   // [B, D]
    const float* __restrict__ enc_out, // [B, T, D]
    float* __restrict__ out            // [B, D], pre-zeroed
) {
    __shared__ float s_dec[DD];          // dec * log2e
    __shared__ float s_rp[DD][17];       // row partials (16 per row, lane-pair combined)
    __shared__ float s_cp[8][DD];        // colsum partials per row-part

    const int bt  = blockIdx.x;          // b*T + t
    const int b   = bt >> 7;
    const int tid = threadIdx.x;
    const int cg  = tid & 31;            // col group (8 cols) = lane
    const int rp  = tid >> 5;            // row part (32 rows) = warp

    const float L2E = 1.4426950408889634f;
    s_dec[tid] = dec_t[b * DD + tid] * L2E;

    const float4 xa = *(const float4*)(enc_out + bt * DD + cg * 8);
    const float4 xb = *(const float4*)(enc_out + bt * DD + cg * 8 + 4);

    __syncthreads();

    float2 c01 = make_float2(0.f, 0.f), c23 = make_float2(0.f, 0.f);
    float2 c45 = make_float2(0.f, 0.f), c67 = make_float2(0.f, 0.f);

    const float* dbase = &s_dec[rp * 32];
    float* rbase = &s_rp[rp * 32][cg >> 1];
    const bool wlane = ((cg & 1) == 0);

#pragma unroll
    for (int i = 0; i < 32; i++) {
        const float d = dbase[i];               // warp-uniform, immediate offset
        float2 e01, e23, e45, e67;
        e01.x = ex2f(d * xa.x);  e01.y = ex2f(d * xa.y);
        e23.x = ex2f(d * xa.z);  e23.y = ex2f(d * xa.w);
        e45.x = ex2f(d * xb.x);  e45.y = ex2f(d * xb.y);
        e67.x = ex2f(d * xb.z);
        e67.y = ex2_poly(d, xb.w);              // fma-pipe path (1 of 8)
        c01 = padd2(c01, e01);   c23 = padd2(c23, e23);
        c45 = padd2(c45, e45);   c67 = padd2(c67, e67);
        const float2 sa = padd2(padd2(e01, e23), padd2(e45, e67));
        float r8 = sa.x + sa.y;
        r8 += __shfl_xor_sync(0xffffffffu, r8, 1, 32);
        if (wlane) rbase[i * 17] = r8;           // immediate-offset STS, 16 banks
    }

    // spill colsum partials (2x STS.128)
    *(float4*)&s_cp[rp][cg * 8]     = make_float4(c01.x, c01.y, c23.x, c23.y);
    *(float4*)&s_cp[rp][cg * 8 + 4] = make_float4(c45.x, c45.y, c67.x, c67.y);
    __syncthreads();

    // rowsum of row tid (same thread outputs column q = tid)
    float rs = 0.f;
#pragma unroll
    for (int j = 0; j < 16; j++) rs += s_rp[tid][j];   // stride-17: conflict-free

    float cs = 0.f;
#pragma unroll
    for (int r = 0; r < 8; r++) cs += s_cp[r][tid];

    const float x = enc_out[bt * DD + tid];
    atomicAdd(&out[b * DD + tid], __fdividef(x * cs, rs));
}

extern "C" void kernel_launch(void* const* d_in, const int* in_sizes, int n_in,
                              void* d_out, int out_size) {
    const float* dec_t   = (const float*)d_in[0];
    const float* enc_out = (const float*)d_in[1];
    if (n_in >= 2 && in_sizes[0] == BB * TT * DD && in_sizes[1] == BB * DD) {
        dec_t   = (const float*)d_in[1];
        enc_out = (const float*)d_in[0];
    }
    float* out = (float*)d_out;

    cudaMemsetAsync(out, 0, BB * DD * sizeof(float), 0);
    attn_fused_kernel<<<BB * TT, DD>>>(dec_t, enc_out, out);
}